// round 1
// baseline (speedup 1.0000x reference)
#include <cuda_runtime.h>

// GSA_69063074119914 — scalar-channel spatial-reduction attention.
// B=16, C=1, H=W=128, PATCH=8 -> HW=16384 queries, hw=256 keys per batch.
// out[b,s] = sum_t softmax_t(q_s * k_t) * v_t,  q = wq*x+bq, k/v = affine(conv(x)).

#define NB   16
#define NT   256      // keys per batch (16x16)
#define HW   16384    // queries per batch
#define LOG2E 1.4426950408889634f

// Scratch (device globals — no allocation allowed in kernel_launch).
__device__ float2 g_kv[NB][NT];   // x = k * log2(e), y = v
__device__ float2 g_mm[NB];       // x = max(k2), y = min(k2)

__global__ void gsa_prep_kernel(const float* __restrict__ x,
                                const float* __restrict__ wk, const float* __restrict__ bk,
                                const float* __restrict__ wv, const float* __restrict__ bv,
                                const float* __restrict__ cw, const float* __restrict__ cb)
{
    __shared__ float s_cw[64];
    __shared__ float s_red[NT];
    const int b = blockIdx.x;
    const int t = threadIdx.x;

    if (t < 64) s_cw[t] = cw[t];
    __syncthreads();

    // conv2d(1,1,k=8,stride=8): thread t -> downsampled cell (i,j)
    const int i = t >> 4;
    const int j = t & 15;
    const float* xb = x + (size_t)b * HW + (i * 8) * 128 + j * 8;
    float ds = 0.f;
#pragma unroll
    for (int p = 0; p < 8; ++p)
#pragma unroll
        for (int q = 0; q < 8; ++q)
            ds = fmaf(xb[p * 128 + q], s_cw[p * 8 + q], ds);
    ds += cb[0];

    const float k2 = fmaf(wk[0], ds, bk[0]) * LOG2E;   // pre-scaled for ex2
    const float v  = fmaf(wv[0], ds, bv[0]);
    g_kv[b][t] = make_float2(k2, v);

    // block max of k2
    s_red[t] = k2;
    __syncthreads();
#pragma unroll
    for (int off = 128; off > 0; off >>= 1) {
        if (t < off) s_red[t] = fmaxf(s_red[t], s_red[t + off]);
        __syncthreads();
    }
    const float kmax = s_red[0];
    __syncthreads();

    // block min of k2
    s_red[t] = k2;
    __syncthreads();
#pragma unroll
    for (int off = 128; off > 0; off >>= 1) {
        if (t < off) s_red[t] = fminf(s_red[t], s_red[t + off]);
        __syncthreads();
    }
    if (t == 0) g_mm[b] = make_float2(kmax, s_red[0]);
}

__global__ void __launch_bounds__(256) gsa_attn_kernel(
        const float* __restrict__ x,
        const float* __restrict__ wq, const float* __restrict__ bq,
        float* __restrict__ out)
{
    __shared__ float2 s_kv[NT];
    const int b   = blockIdx.y;
    const int tid = threadIdx.x;

    s_kv[tid] = g_kv[b][tid];
    __syncthreads();

    const float2 mm = g_mm[b];
    const int   s   = blockIdx.x * 256 + tid;
    const float qn  = fmaf(wq[0], x[(size_t)b * HW + s], bq[0]);
    // exact running max of q*k2 over t: attained at k2max or k2min (sign of qn)
    const float m2  = fmaxf(qn * mm.x, qn * mm.y);

    float num0 = 0.f, num1 = 0.f, den0 = 0.f, den1 = 0.f;
#pragma unroll 8
    for (int t = 0; t < NT; t += 2) {
        float2 kv0 = s_kv[t];
        float2 kv1 = s_kv[t + 1];
        float e0, e1;
        float a0 = fmaf(qn, kv0.x, -m2);
        float a1 = fmaf(qn, kv1.x, -m2);
        asm("ex2.approx.f32 %0, %1;" : "=f"(e0) : "f"(a0));
        asm("ex2.approx.f32 %0, %1;" : "=f"(e1) : "f"(a1));
        num0 = fmaf(e0, kv0.y, num0);
        num1 = fmaf(e1, kv1.y, num1);
        den0 += e0;
        den1 += e1;
    }
    out[(size_t)b * HW + s] = (num0 + num1) / (den0 + den1);
}

extern "C" void kernel_launch(void* const* d_in, const int* in_sizes, int n_in,
                              void* d_out, int out_size)
{
    // metadata order: x, wq, bq, wk, bk, wv, bv, conv_w, conv_b
    const float* x  = (const float*)d_in[0];
    const float* wq = (const float*)d_in[1];
    const float* bq = (const float*)d_in[2];
    const float* wk = (const float*)d_in[3];
    const float* bk = (const float*)d_in[4];
    const float* wv = (const float*)d_in[5];
    const float* bv = (const float*)d_in[6];
    const float* cw = (const float*)d_in[7];
    const float* cb = (const float*)d_in[8];
    float* out = (float*)d_out;

    gsa_prep_kernel<<<NB, NT>>>(x, wk, bk, wv, bv, cw, cb);
    gsa_attn_kernel<<<dim3(HW / 256, NB), 256>>>(x, wq, bq, out);
}

// round 2
// speedup vs baseline: 1.4953x; 1.4953x over previous
#include <cuda_runtime.h>

// GSA_69063074119914 — scalar-channel spatial-reduction attention, tabulated.
// Key insight: d=1 => out[b,s] = f_b(q_s), a smooth scalar function defined by
// 256 (k,v) pairs per batch. Build f_b and f_b' on a per-batch grid (exact
// q-range from data), evaluate queries with cubic Hermite interpolation.

#define NB    16
#define NT    256      // keys per batch
#define HW    16384    // queries per batch
#define NPTS  2048     // table nodes per batch
#define LOG2E 1.4426950408889634f
#define LN2   0.6931471805599453f

// Device-global scratch (no allocation allowed in kernel_launch).
__device__ float2 g_kv[NB][NT];       // x = k*log2(e), y = v
__device__ float2 g_mm[NB];           // x = max(k2), y = min(k2)
__device__ float2 g_qr[NB];           // x = qlo, y = qhi
__device__ float2 g_tab[NB][NPTS];    // x = f(q_n), y = f'(q_n)

// ---------------------------------------------------------------------------
// Kernel 1: per-batch prep. conv8x8/s8 -> (k,v); k2 min/max; exact q range.
// One block per batch.
__global__ void __launch_bounds__(256) gsa_prep_kernel(
        const float* __restrict__ x,
        const float* __restrict__ wq, const float* __restrict__ bq,
        const float* __restrict__ wk, const float* __restrict__ bk,
        const float* __restrict__ wv, const float* __restrict__ bv,
        const float* __restrict__ cw, const float* __restrict__ cb)
{
    __shared__ float s_cw[64];
    __shared__ float s_a[NT];
    __shared__ float s_b[NT];
    const int b = blockIdx.x;
    const int t = threadIdx.x;

    if (t < 64) s_cw[t] = cw[t];
    __syncthreads();

    // ---- conv: thread t -> downsampled cell (i,j) ----
    const int i = t >> 4;
    const int j = t & 15;
    const float* xb = x + (size_t)b * HW + (i * 8) * 128 + j * 8;
    float ds = 0.f;
#pragma unroll
    for (int p = 0; p < 8; ++p)
#pragma unroll
        for (int q = 0; q < 8; ++q)
            ds = fmaf(xb[p * 128 + q], s_cw[p * 8 + q], ds);
    ds += cb[0];

    const float k2 = fmaf(wk[0], ds, bk[0]) * LOG2E;
    const float v  = fmaf(wv[0], ds, bv[0]);
    g_kv[b][t] = make_float2(k2, v);

    // ---- x min/max over this batch (coalesced grid-stride within block) ----
    const float* xrow = x + (size_t)b * HW;
    float xmn = xrow[t], xmx = xmn;
#pragma unroll 4
    for (int it = 1; it < HW / 256; ++it) {
        float xv = xrow[it * 256 + t];
        xmn = fminf(xmn, xv);
        xmx = fmaxf(xmx, xv);
    }

    // ---- joint block reductions: (k2max, k2min) and (xmax, xmin) ----
    s_a[t] = k2;  s_b[t] = xmx;
    __syncthreads();
#pragma unroll
    for (int off = 128; off > 0; off >>= 1) {
        if (t < off) {
            s_a[t] = fmaxf(s_a[t], s_a[t + off]);
            s_b[t] = fmaxf(s_b[t], s_b[t + off]);
        }
        __syncthreads();
    }
    const float k2max = s_a[0], xmax = s_b[0];
    __syncthreads();

    s_a[t] = k2;  s_b[t] = xmn;
    __syncthreads();
#pragma unroll
    for (int off = 128; off > 0; off >>= 1) {
        if (t < off) {
            s_a[t] = fminf(s_a[t], s_a[t + off]);
            s_b[t] = fminf(s_b[t], s_b[t + off]);
        }
        __syncthreads();
    }
    if (t == 0) {
        g_mm[b] = make_float2(k2max, s_a[0]);
        const float q1 = fmaf(wq[0], s_b[0], bq[0]);   // q at xmin
        const float q2 = fmaf(wq[0], xmax,  bq[0]);    // q at xmax
        g_qr[b] = make_float2(fminf(q1, q2), fmaxf(q1, q2));
    }
}

// ---------------------------------------------------------------------------
// Kernel 2: build f/f' table. One thread per node. grid = (NPTS/256, NB).
__global__ void __launch_bounds__(256) gsa_table_kernel()
{
    __shared__ float2 s_kv[NT];
    const int b = blockIdx.y;
    const int t = threadIdx.x;

    s_kv[t] = g_kv[b][t];
    __syncthreads();

    const float2 qr = g_qr[b];
    const float2 mm = g_mm[b];
    const int   n   = blockIdx.x * 256 + t;
    const float h   = (qr.y - qr.x) * (1.0f / (NPTS - 1));
    const float qn  = qr.x + h * (float)n;
    const float m2  = fmaxf(qn * mm.x, qn * mm.y);   // exact max exponent

    float S0 = 0.f, S1 = 0.f, S2 = 0.f, S3 = 0.f;
#pragma unroll 8
    for (int u = 0; u < NT; ++u) {
        float2 kv = s_kv[u];
        float a = fmaf(qn, kv.x, -m2);
        float e;
        asm("ex2.approx.f32 %0, %1;" : "=f"(e) : "f"(a));
        float ve = kv.y * e;
        S0 += e;
        S1 += ve;
        S2 = fmaf(kv.x, e,  S2);
        S3 = fmaf(kv.x, ve, S3);
    }
    const float r  = __frcp_rn(S0);
    const float f  = S1 * r;
    const float fp = LN2 * r * fmaf(-f, S2, S3);   // df/dq
    g_tab[b][n] = make_float2(f, fp);
}

// ---------------------------------------------------------------------------
// Kernel 3: evaluate queries via cubic Hermite. grid = (HW/256, NB).
__global__ void __launch_bounds__(256) gsa_query_kernel(
        const float* __restrict__ x,
        const float* __restrict__ wq, const float* __restrict__ bq,
        float* __restrict__ out)
{
    const int b   = blockIdx.y;
    const int s   = blockIdx.x * 256 + threadIdx.x;
    const size_t idx = (size_t)b * HW + s;

    const float2 qr    = g_qr[b];
    const float  range = qr.y - qr.x;
    const float  hstep = range * (1.0f / (NPTS - 1));
    const float  scale = (range > 0.f) ? (NPTS - 1) / range : 0.f;

    const float q = fmaf(wq[0], x[idx], bq[0]);
    float tpos = (q - qr.x) * scale;
    tpos = fminf(fmaxf(tpos, 0.f), (float)(NPTS - 1));
    int i = (int)tpos;
    i = min(i, NPTS - 2);
    const float u = tpos - (float)i;

    const float2 n0 = g_tab[b][i];
    const float2 n1 = g_tab[b][i + 1];
    const float m0 = n0.y * hstep;
    const float m1 = n1.y * hstep;
    const float d  = n1.x - n0.x;

    // p(u) = f0 + u*(m0 + u*((3d - 2m0 - m1) + u*(m0 + m1 - 2d)))
    const float c2 = 3.f * d - 2.f * m0 - m1;
    const float c3 = m0 + m1 - 2.f * d;
    const float pu = fmaf(u, fmaf(u, fmaf(u, c3, c2), m0), n0.x);

    out[idx] = pu;
}

extern "C" void kernel_launch(void* const* d_in, const int* in_sizes, int n_in,
                              void* d_out, int out_size)
{
    // metadata order: x, wq, bq, wk, bk, wv, bv, conv_w, conv_b
    const float* x  = (const float*)d_in[0];
    const float* wq = (const float*)d_in[1];
    const float* bq = (const float*)d_in[2];
    const float* wk = (const float*)d_in[3];
    const float* bk = (const float*)d_in[4];
    const float* wv = (const float*)d_in[5];
    const float* bv = (const float*)d_in[6];
    const float* cw = (const float*)d_in[7];
    const float* cb = (const float*)d_in[8];
    float* out = (float*)d_out;

    gsa_prep_kernel<<<NB, 256>>>(x, wq, bq, wk, bk, wv, bv, cw, cb);
    gsa_table_kernel<<<dim3(NPTS / 256, NB), 256>>>();
    gsa_query_kernel<<<dim3(HW / 256, NB), 256>>>(x, wq, bq, out);
}